// round 1
// baseline (speedup 1.0000x reference)
#include <cuda_runtime.h>
#include <math.h>

#define BSZ 128
#define HD 64
#define NTREE 4095
#define FIVEH 320
#define KD 128
#define TM 32
#define NTHREADS 256
#define SMEM_BYTES ((40960 + TM * KD) * 4)

typedef unsigned long long ull;

// Ping-pong level state. 4 x 64 MiB static device arrays (allowed scratch).
__device__ float g_h[2][(size_t)BSZ * 2048 * HD];
__device__ float g_c[2][(size_t)BSZ * 2048 * HD];

__device__ __forceinline__ float sigf(float x) {
    return __fdividef(1.f, 1.f + __expf(-x));
}
__device__ __forceinline__ float tanh_fast(float x) {
    float ax = fabsf(x);
    float e = __expf(-2.f * ax);
    float t = __fdividef(1.f - e, 1.f + e);
    return x < 0.f ? -t : t;
}
__device__ __forceinline__ void ffma2(ull& d, ull a, ull b) {
    asm("fma.rn.f32x2 %0, %1, %2, %0;" : "+l"(d) : "l"(a), "l"(b));
}

// ---------------- Leaf level (d=11): z = Wx[idx] + b; c = sig(i)*tanh(u); h = sig(o)*tanh(c)
__global__ void leaf_kernel(const int* __restrict__ x_idx,
                            const float* __restrict__ Wx,
                            const float* __restrict__ bt) {
    int id = blockIdx.x * blockDim.x + threadIdx.x;  // (m, col) flattened
    int col = id & 63;
    int m = id >> 6;
    int b = m >> 11;
    int jl = m & 2047;
    int idx = x_idx[b * NTREE + 2047 + jl];
    const float* w = Wx + idx * FIVEH;
    float zi = w[col] + bt[col];
    float zo = w[192 + col] + bt[192 + col];
    float zu = w[256 + col] + bt[256 + col];
    float c = sigf(zi) * tanh_fast(zu);
    float h = sigf(zo) * tanh_fast(c);
    g_h[1][id] = h;
    g_c[1][id] = c;
}

// ---------------- Internal level d: persistent CTAs, full U in smem, f32x2 FMA
__global__ void level_kernel(int d, const int* __restrict__ x_idx,
                             const float* __restrict__ Wx,
                             const float* __restrict__ Ua,
                             const float* __restrict__ Ub,
                             const float* __restrict__ bt,
                             int pin, int pout) {
    extern __shared__ float smem[];
    float* sU = smem;            // [128][320]  rows 0..63 = Ua, 64..127 = Ub
    float* sH = smem + 40960;    // [TM][128]   child pair rows (contiguous)
    const float* __restrict__ hchild = g_h[pin];
    const float* __restrict__ cchild = g_c[pin];
    float* __restrict__ hout = g_h[pout];
    float* __restrict__ cout = g_c[pout];

    int tid = threadIdx.x;
    for (int i = tid; i < 20480; i += NTHREADS) sU[i] = Ua[i];
    for (int i = tid; i < 20480; i += NTHREADS) sU[20480 + i] = Ub[i];
    __syncthreads();

    const int n = 1 << d;
    const int off = n - 1;
    const int tiles = (BSZ * n) / TM;   // always exact: M = 128*n
    const int jp = tid & 31;            // column pair: cols (2jp, 2jp+1)
    const int mg = tid >> 5;            // node group 0..7, 4 nodes each

    float btr[5][2];
#pragma unroll
    for (int g = 0; g < 5; ++g) {
        float2 bv = *(const float2*)(bt + g * 64 + 2 * jp);
        btr[g][0] = bv.x;
        btr[g][1] = bv.y;
    }

    for (int t = blockIdx.x; t < tiles; t += gridDim.x) {
        int m0 = t * TM;
        // A tile: rows m0..m0+31, each = hchild[2m*64 .. 2m*64+127] (contiguous)
        const float4* src = (const float4*)(hchild + (size_t)m0 * 128);
        float4* dst = (float4*)sH;
        for (int i = tid; i < (TM * KD) / 4; i += NTHREADS) dst[i] = src[i];
        __syncthreads();

        ull acc[4][5];
#pragma unroll
        for (int r = 0; r < 4; ++r)
#pragma unroll
            for (int g = 0; g < 5; ++g) acc[r][g] = 0ull;

#pragma unroll 4
        for (int k = 0; k < KD; ++k) {
            const float* uk = sU + k * FIVEH + 2 * jp;
            ull u0 = *(const ull*)(uk);
            ull u1 = *(const ull*)(uk + 64);
            ull u2 = *(const ull*)(uk + 128);
            ull u3 = *(const ull*)(uk + 192);
            ull u4 = *(const ull*)(uk + 256);
#pragma unroll
            for (int r = 0; r < 4; ++r) {
                float hv = sH[(mg * 4 + r) * KD + k];
                unsigned hb = __float_as_uint(hv);
                ull hp;
                asm("mov.b64 %0, {%1, %2};" : "=l"(hp) : "r"(hb), "r"(hb));
                ffma2(acc[r][0], hp, u0);
                ffma2(acc[r][1], hp, u1);
                ffma2(acc[r][2], hp, u2);
                ffma2(acc[r][3], hp, u3);
                ffma2(acc[r][4], hp, u4);
            }
        }

#pragma unroll
        for (int r = 0; r < 4; ++r) {
            int m = m0 + mg * 4 + r;
            int b = m >> d;
            int jl = m & (n - 1);
            int idx = x_idx[b * NTREE + off + jl];
            const float* w = Wx + idx * FIVEH + 2 * jp;
            float z[5][2];
#pragma unroll
            for (int g = 0; g < 5; ++g) {
                unsigned ulo, uhi;
                asm("mov.b64 {%0, %1}, %2;" : "=r"(ulo), "=r"(uhi) : "l"(acc[r][g]));
                float2 wv = *(const float2*)(w + g * 64);
                z[g][0] = __uint_as_float(ulo) + wv.x + btr[g][0];
                z[g][1] = __uint_as_float(uhi) + wv.y + btr[g][1];
            }
            float2 ca = *(const float2*)(cchild + (size_t)(2 * m) * 64 + 2 * jp);
            float2 cb = *(const float2*)(cchild + (size_t)(2 * m) * 64 + 64 + 2 * jp);
            float c0 = sigf(z[0][0]) * tanh_fast(z[4][0]) + sigf(z[1][0]) * ca.x + sigf(z[2][0]) * cb.x;
            float c1 = sigf(z[0][1]) * tanh_fast(z[4][1]) + sigf(z[1][1]) * ca.y + sigf(z[2][1]) * cb.y;
            float h0 = sigf(z[3][0]) * tanh_fast(c0);
            float h1 = sigf(z[3][1]) * tanh_fast(c1);
            *(float2*)(hout + (size_t)m * 64 + 2 * jp) = make_float2(h0, h1);
            *(float2*)(cout + (size_t)m * 64 + 2 * jp) = make_float2(c0, c1);
        }
        __syncthreads();
    }
}

// ---------------- Head: MLP -> LSTM cell (h0=0 so W_hh drops) -> actor -> softmax(T=3)
__global__ void head_kernel(const float* __restrict__ W1, const float* __restrict__ b1,
                            const float* __restrict__ W2, const float* __restrict__ b2,
                            const float* __restrict__ W_ih, const float* __restrict__ b_lstm,
                            const float* __restrict__ actorW, const float* __restrict__ actorb,
                            const float* __restrict__ vm, float* __restrict__ out) {
    __shared__ float sh[64], sf1[64], sfeat[128], slog[20], sinv[1];
    int b = blockIdx.x;
    int t = threadIdx.x;  // 64 threads
    sh[t] = g_h[0][b * 64 + t];
    __syncthreads();
    float a = 0.f;
    for (int k = 0; k < 64; ++k) a += sh[k] * W1[k * 64 + t];
    a += b1[t];
    sf1[t] = fmaxf(a, 0.f);
    __syncthreads();
    float f = 0.f;
    for (int k = 0; k < 64; ++k) f += sf1[k] * W2[k * 64 + t];
    f += b2[t];
    sfeat[t] = f;
    __syncthreads();
    float gi = 0.f, gg = 0.f, go = 0.f;
    for (int k = 0; k < 64; ++k) {
        float fk = sfeat[k];
        gi += fk * W_ih[k * 256 + t];
        gg += fk * W_ih[k * 256 + 128 + t];
        go += fk * W_ih[k * 256 + 192 + t];
    }
    gi += b_lstm[t];
    gg += b_lstm[128 + t];
    go += b_lstm[192 + t];
    float cg = (1.f / (1.f + expf(-gi))) * tanhf(gg);
    float hg = (1.f / (1.f + expf(-go))) * tanhf(cg);
    sfeat[64 + t] = hg;
    __syncthreads();
    if (t < 20) {
        float l = 0.f;
        for (int dd = 0; dd < 128; ++dd) l += sfeat[dd] * actorW[dd * 20 + t];
        l = logf(vm[t]) + l * vm[t] + actorb[t] * vm[t];
        slog[t] = l / 3.0f;
    }
    __syncthreads();
    if (t == 0) {
        float mx = slog[0];
        for (int k = 1; k < 20; ++k) mx = fmaxf(mx, slog[k]);
        float s = 0.f;
        for (int k = 0; k < 20; ++k) {
            float e = expf(slog[k] - mx);
            slog[k] = e;
            s += e;
        }
        sinv[0] = 1.f / s;
    }
    __syncthreads();
    if (t < 20) out[b * 20 + t] = slog[t] * sinv[0];
}

extern "C" void kernel_launch(void* const* d_in, const int* in_sizes, int n_in,
                              void* d_out, int out_size) {
    const int*   x_idx  = (const int*)d_in[0];
    const float* vm     = (const float*)d_in[1];
    const float* Wx     = (const float*)d_in[2];
    const float* Ua     = (const float*)d_in[3];
    const float* Ub     = (const float*)d_in[4];
    const float* bt     = (const float*)d_in[5];
    const float* W_ih   = (const float*)d_in[6];
    // d_in[7] = W_hh (unused: h0 == 0)
    const float* b_lstm = (const float*)d_in[8];
    const float* W1     = (const float*)d_in[9];
    const float* b1     = (const float*)d_in[10];
    const float* W2     = (const float*)d_in[11];
    const float* b2     = (const float*)d_in[12];
    const float* actorW = (const float*)d_in[13];
    const float* actorb = (const float*)d_in[14];
    float* out = (float*)d_out;

    cudaFuncSetAttribute(level_kernel, cudaFuncAttributeMaxDynamicSharedMemorySize,
                         SMEM_BYTES);

    // Leaf level d=11 -> buffers parity 1
    leaf_kernel<<<(BSZ * 2048 * HD) / NTHREADS, NTHREADS>>>(x_idx, Wx, bt);

    // Internal levels d=10..0, ping-pong parity d&1 (child = (d+1)&1)
    for (int d = 10; d >= 0; --d) {
        int tiles = (BSZ << d) / TM;
        int grid = tiles < 152 ? tiles : 152;
        level_kernel<<<grid, NTHREADS, SMEM_BYTES>>>(d, x_idx, Wx, Ua, Ub, bt,
                                                     (d + 1) & 1, d & 1);
    }

    head_kernel<<<BSZ, 64>>>(W1, b1, W2, b2, W_ih, b_lstm, actorW, actorb, vm, out);
}

// round 3
// speedup vs baseline: 1.8486x; 1.8486x over previous
#include <cuda_runtime.h>
#include <math.h>
#include <cstdint>

#define BSZ 128
#define NTREE 4095
#define NT 512

// smem byte layout:
//   [1024 .. 66560)  A fragment planes (4 x 16KB)   -- overlaid by:
//   [1024 .. 34816)  zbuf0   [34816 .. 68608) zbuf1 (128 x 66 floats each)
//   [68608 .. 232448) B fragment image (160KB)
#define ROFF 1024
#define ZB0 1024
#define ZB1 34816
#define BOFF 68608
#define SMEM_TOTAL 232448
#define ZSTRIDE 66

// ping-pong level state + fragment-ordered tf32 U image
__device__ float g_h[2][(size_t)BSZ * 2048 * 64];
__device__ float g_c[2][(size_t)BSZ * 2048 * 64];
__device__ float g_Bfrag[40960];

__device__ __forceinline__ float sigf(float x) {
    return __fdividef(1.f, 1.f + __expf(-x));
}
__device__ __forceinline__ float tanh_fast(float x) {
    float ax = fabsf(x);
    float e = __expf(-2.f * ax);
    float t = __fdividef(1.f - e, 1.f + e);
    return x < 0.f ? -t : t;
}
__device__ __forceinline__ float tf32r(float x) {
    asm("cvt.rna.tf32.f32 %0, %1;" : "=f"(x) : "f"(x));
    return x;
}
__device__ __forceinline__ void mma_tf32(float c[4], const uint32_t a[4],
                                         uint32_t b0, uint32_t b1) {
    asm volatile(
        "mma.sync.aligned.m16n8k8.row.col.f32.tf32.tf32.f32 "
        "{%0,%1,%2,%3}, {%4,%5,%6,%7}, {%8,%9}, {%0,%1,%2,%3};"
        : "+f"(c[0]), "+f"(c[1]), "+f"(c[2]), "+f"(c[3])
        : "r"(a[0]), "r"(a[1]), "r"(a[2]), "r"(a[3]), "r"(b0), "r"(b1));
}

// ---------------- build fragment-ordered tf32 U image (once per launch)
// element id -> (g, wn, ks2, lane, slot); slot: {b0,b1} of kstep 2*ks2 then 2*ks2+1
__global__ void bprep_kernel(const float* __restrict__ Ua, const float* __restrict__ Ub) {
    int id = blockIdx.x * blockDim.x + threadIdx.x;   // 40960
    int slot = id & 3;
    int lane = (id >> 2) & 31;
    int ks2  = (id >> 7) & 7;
    int wn   = (id >> 10) & 7;
    int g    = id >> 13;
    int kstep = ks2 * 2 + (slot >> 1);
    int j = slot & 1;                       // b0 / b1
    int k = kstep * 8 + (lane & 3) + 4 * j;
    int n = g * 64 + wn * 8 + (lane >> 2);
    float v = (k < 64) ? Ua[k * 320 + n] : Ub[(k - 64) * 320 + n];
    g_Bfrag[id] = tf32r(v);
}

// ---------------- leaf level d=11
__global__ void leaf_kernel(const int* __restrict__ x_idx,
                            const float* __restrict__ Wx,
                            const float* __restrict__ bt) {
    int id = blockIdx.x * blockDim.x + threadIdx.x;   // B*2048*16
    int q = id & 15;
    int m = id >> 4;
    int b = m >> 11, jl = m & 2047;
    int idx = x_idx[b * NTREE + 2047 + jl];
    const float* w = Wx + idx * 320;
    int c4 = q * 4;
    float4 wi = *(const float4*)(w + c4),        bi = *(const float4*)(bt + c4);
    float4 wo = *(const float4*)(w + 192 + c4),  bo = *(const float4*)(bt + 192 + c4);
    float4 wu = *(const float4*)(w + 256 + c4),  bu = *(const float4*)(bt + 256 + c4);
    float ci[4], hi[4];
    float zi[4] = {wi.x + bi.x, wi.y + bi.y, wi.z + bi.z, wi.w + bi.w};
    float zo[4] = {wo.x + bo.x, wo.y + bo.y, wo.z + bo.z, wo.w + bo.w};
    float zu[4] = {wu.x + bu.x, wu.y + bu.y, wu.z + bu.z, wu.w + bu.w};
#pragma unroll
    for (int e = 0; e < 4; ++e) {
        ci[e] = sigf(zi[e]) * tanh_fast(zu[e]);
        hi[e] = tf32r(sigf(zo[e]) * tanh_fast(ci[e]));
    }
    *(float4*)(g_h[1] + (size_t)m * 64 + c4) = make_float4(hi[0], hi[1], hi[2], hi[3]);
    *(float4*)(g_c[1] + (size_t)m * 64 + c4) = make_float4(ci[0], ci[1], ci[2], ci[3]);
}

// ---------------- one 128-row tile: A-fill, MMA, staged epilogue
__device__ __forceinline__ void tile_step(
    char* smem, int nvalid, const int* __restrict__ idxp,
    const float* __restrict__ asrc,   // hchild + m0*128
    const float* __restrict__ csrc,   // cchild + m0*128
    float* __restrict__ houtp,        // hout + m0*64
    float* __restrict__ coutp,
    const float* __restrict__ Wx,
    const float bias[5][2]) {
    const int tid = threadIdx.x;
    const int wid = tid >> 5, lane = tid & 31;
    const int wm = wid >> 3, wn = wid & 7;
    const int mrow0 = wm * 64;

    // ---- A fill into fragment planes
#pragma unroll
    for (int i = 0; i < 8; ++i) {
        int f = tid + i * NT;
        int row = f >> 5, q = f & 31;
        float4 v = make_float4(0.f, 0.f, 0.f, 0.f);
        if (row < nvalid) v = ((const float4*)asrc)[f];
        int reg = ((q & 1) << 1) | ((row >> 3) & 1);
        int ks = q >> 1, mf = row >> 4;
        *(float4*)(smem + ROFF + reg * 16384 +
                   (((mf * 16 + ks) * 32 + ((row & 7) << 2)) << 2)) = v;
    }
    __syncthreads();

    // ---- MMA: warp (wm,wn) -> rows [wm*64,+64), cols {g*64 + wn*8 .. +8}
    float acc[4][5][4] = {};
    const char* aP = smem + ROFF;
    const char* bP = smem + BOFF;
#pragma unroll
    for (int ks2 = 0; ks2 < 8; ++ks2) {
#pragma unroll
        for (int half = 0; half < 2; ++half) {
            int ks = ks2 * 2 + half;
            uint32_t a[4][4];
#pragma unroll
            for (int mfl = 0; mfl < 4; ++mfl) {
                if (mrow0 + mfl * 16 < nvalid) {
                    int base = (((wm * 4 + mfl) * 16 + ks) * 32 + lane) * 4;
#pragma unroll
                    for (int j = 0; j < 4; ++j)
                        a[mfl][j] = *(const uint32_t*)(aP + j * 16384 + base);
                }
            }
#pragma unroll
            for (int g = 0; g < 5; ++g) {
                uint2 bv = *(const uint2*)(bP + ((((g * 8 + wn) * 8 + ks2) * 32 + lane) << 4)
                                           + half * 8);
#pragma unroll
                for (int mfl = 0; mfl < 4; ++mfl)
                    if (mrow0 + mfl * 16 < nvalid)
                        mma_tf32(acc[mfl][g], a[mfl], bv.x, bv.y);
            }
        }
    }
    __syncthreads();   // all warps done reading A planes before z-staging reuses them

    // ---- staged epilogue
    const int jp = lane;            // cols 2jp, 2jp+1
    const int prow = wid * 8;       // 8 rows per warp
    const float* wrow[8];
#pragma unroll
    for (int rr = 0; rr < 8; ++rr) {
        int row = prow + rr;
        int idx = (row < nvalid) ? idxp[row] : 0;
        wrow[rr] = Wx + idx * 320 + 2 * jp;
    }

#define STOREG(g, buf)                                                            \
    {                                                                             \
        _Pragma("unroll")                                                         \
        for (int mfl = 0; mfl < 4; ++mfl) {                                       \
            if (mrow0 + mfl * 16 < nvalid) {                                      \
                int row = mrow0 + mfl * 16 + (lane >> 2);                         \
                int col = wn * 8 + 2 * (lane & 3);                                \
                *(float2*)(smem + (buf) + (row * ZSTRIDE + col) * 4) =            \
                    make_float2(acc[mfl][g][0], acc[mfl][g][1]);                  \
                *(float2*)(smem + (buf) + ((row + 8) * ZSTRIDE + col) * 4) =      \
                    make_float2(acc[mfl][g][2], acc[mfl][g][3]);                  \
            }                                                                     \
        }                                                                         \
    }

    // phase A: gates u(4) -> ZB0, i(0) -> ZB1
    STOREG(4, ZB0)
    STOREG(0, ZB1)
    __syncthreads();
    float cn0[8], cn1[8];
#pragma unroll
    for (int rr = 0; rr < 8; ++rr) {
        int row = prow + rr;
        if (row < nvalid) {
            float2 zu = *(float2*)(smem + ZB0 + (row * ZSTRIDE + 2 * jp) * 4);
            float2 zi = *(float2*)(smem + ZB1 + (row * ZSTRIDE + 2 * jp) * 4);
            float2 wu = *(const float2*)(wrow[rr] + 256);
            float2 wi = *(const float2*)(wrow[rr]);
            cn0[rr] = sigf(zi.x + wi.x + bias[0][0]) * tanh_fast(zu.x + wu.x + bias[4][0]);
            cn1[rr] = sigf(zi.y + wi.y + bias[0][1]) * tanh_fast(zu.y + wu.y + bias[4][1]);
        }
    }
    __syncthreads();

    // phase B: gates fa(1) -> ZB0, fb(2) -> ZB1
    STOREG(1, ZB0)
    STOREG(2, ZB1)
    __syncthreads();
#pragma unroll
    for (int rr = 0; rr < 8; ++rr) {
        int row = prow + rr;
        if (row < nvalid) {
            float2 za = *(float2*)(smem + ZB0 + (row * ZSTRIDE + 2 * jp) * 4);
            float2 zb = *(float2*)(smem + ZB1 + (row * ZSTRIDE + 2 * jp) * 4);
            float2 wa = *(const float2*)(wrow[rr] + 64);
            float2 wb = *(const float2*)(wrow[rr] + 128);
            const float* crow = csrc + (size_t)row * 128 + 2 * jp;
            float2 ca = *(const float2*)(crow);
            float2 cb = *(const float2*)(crow + 64);
            cn0[rr] += sigf(za.x + wa.x + bias[1][0]) * ca.x +
                       sigf(zb.x + wb.x + bias[2][0]) * cb.x;
            cn1[rr] += sigf(za.y + wa.y + bias[1][1]) * ca.y +
                       sigf(zb.y + wb.y + bias[2][1]) * cb.y;
        }
    }
    __syncthreads();

    // phase C: gate o(3) -> ZB0
    STOREG(3, ZB0)
    __syncthreads();
#pragma unroll
    for (int rr = 0; rr < 8; ++rr) {
        int row = prow + rr;
        if (row < nvalid) {
            float2 zo = *(float2*)(smem + ZB0 + (row * ZSTRIDE + 2 * jp) * 4);
            float2 wo = *(const float2*)(wrow[rr] + 192);
            float h0 = tf32r(sigf(zo.x + wo.x + bias[3][0]) * tanh_fast(cn0[rr]));
            float h1 = tf32r(sigf(zo.y + wo.y + bias[3][1]) * tanh_fast(cn1[rr]));
            *(float2*)(houtp + (size_t)row * 64 + 2 * jp) = make_float2(h0, h1);
            *(float2*)(coutp + (size_t)row * 64 + 2 * jp) = make_float2(cn0[rr], cn1[rr]);
        }
    }
    __syncthreads();   // protect zbufs / A planes before next tile
#undef STOREG
}

__device__ __forceinline__ void load_common(char* smem, const float* bt, float bias[5][2]) {
    int tid = threadIdx.x;
    const float4* src = (const float4*)g_Bfrag;
    float4* dst = (float4*)(smem + BOFF);
#pragma unroll
    for (int i = 0; i < 20; ++i) dst[tid + i * NT] = src[tid + i * NT];
    int jp = tid & 31;
#pragma unroll
    for (int g = 0; g < 5; ++g) {
        float2 bv = *(const float2*)(bt + g * 64 + 2 * jp);
        bias[g][0] = bv.x;
        bias[g][1] = bv.y;
    }
}

// ---------------- big levels d = 10, 9, 8
__global__ void __launch_bounds__(NT, 1)
level_mma(int d, const int* __restrict__ x_idx, const float* __restrict__ Wx,
          const float* __restrict__ bt, int pin, int pout) {
    extern __shared__ char smem[];
    float bias[5][2];
    load_common(smem, bt, bias);
    __syncthreads();
    const int n = 1 << d;
    const float* hc = g_h[pin];
    const float* cc = g_c[pin];
    float* ho = g_h[pout];
    float* co = g_c[pout];
    for (int t = blockIdx.x; t < n; t += gridDim.x) {
        int m0 = t << 7;
        int b = m0 >> d;
        int jl0 = m0 & (n - 1);
        const int* idxp = x_idx + b * NTREE + (n - 1) + jl0;
        tile_step(smem, 128, idxp, hc + (size_t)m0 * 128, cc + (size_t)m0 * 128,
                  ho + (size_t)m0 * 64, co + (size_t)m0 * 64, Wx, bias);
    }
}

// ---------------- fused top levels d = 7..0, one CTA per batch
__global__ void __launch_bounds__(NT, 1)
top_mma(const int* __restrict__ x_idx, const float* __restrict__ Wx,
        const float* __restrict__ bt) {
    extern __shared__ char smem[];
    float bias[5][2];
    load_common(smem, bt, bias);
    __syncthreads();
    int b = blockIdx.x;
    for (int d = 7; d >= 0; --d) {
        int n = 1 << d;
        int pin = (d + 1) & 1, pout = d & 1;
        const int* idxp = x_idx + b * NTREE + (n - 1);
        size_t cbase = (size_t)b * (2 * n) * 64;   // children rows base
        size_t obase = (size_t)b * n * 64;
        tile_step(smem, n, idxp, g_h[pin] + cbase, g_c[pin] + cbase,
                  g_h[pout] + obase, g_c[pout] + obase, Wx, bias);
    }
}

// ---------------- head
__global__ void head_kernel(const float* __restrict__ W1, const float* __restrict__ b1,
                            const float* __restrict__ W2, const float* __restrict__ b2,
                            const float* __restrict__ W_ih, const float* __restrict__ b_lstm,
                            const float* __restrict__ actorW, const float* __restrict__ actorb,
                            const float* __restrict__ vm, float* __restrict__ out) {
    __shared__ float sh[64], sf1[64], sfeat[128], slog[20], sinv[1];
    int b = blockIdx.x;
    int t = threadIdx.x;
    sh[t] = g_h[0][b * 64 + t];
    __syncthreads();
    float a = 0.f;
    for (int k = 0; k < 64; ++k) a += sh[k] * W1[k * 64 + t];
    a += b1[t];
    sf1[t] = fmaxf(a, 0.f);
    __syncthreads();
    float f = 0.f;
    for (int k = 0; k < 64; ++k) f += sf1[k] * W2[k * 64 + t];
    f += b2[t];
    sfeat[t] = f;
    __syncthreads();
    float gi = 0.f, gg = 0.f, go = 0.f;
    for (int k = 0; k < 64; ++k) {
        float fk = sfeat[k];
        gi += fk * W_ih[k * 256 + t];
        gg += fk * W_ih[k * 256 + 128 + t];
        go += fk * W_ih[k * 256 + 192 + t];
    }
    gi += b_lstm[t];
    gg += b_lstm[128 + t];
    go += b_lstm[192 + t];
    float cg = (1.f / (1.f + expf(-gi))) * tanhf(gg);
    float hg = (1.f / (1.f + expf(-go))) * tanhf(cg);
    sfeat[64 + t] = hg;
    __syncthreads();
    if (t < 20) {
        float l = 0.f;
        for (int dd = 0; dd < 128; ++dd) l += sfeat[dd] * actorW[dd * 20 + t];
        l = logf(vm[t]) + l * vm[t] + actorb[t] * vm[t];
        slog[t] = l / 3.0f;
    }
    __syncthreads();
    if (t == 0) {
        float mx = slog[0];
        for (int k = 1; k < 20; ++k) mx = fmaxf(mx, slog[k]);
        float s = 0.f;
        for (int k = 0; k < 20; ++k) {
            float e = expf(slog[k] - mx);
            slog[k] = e;
            s += e;
        }
        sinv[0] = 1.f / s;
    }
    __syncthreads();
    if (t < 20) out[b * 20 + t] = slog[t] * sinv[0];
}

extern "C" void kernel_launch(void* const* d_in, const int* in_sizes, int n_in,
                              void* d_out, int out_size) {
    const int*   x_idx  = (const int*)d_in[0];
    const float* vm     = (const float*)d_in[1];
    const float* Wx     = (const float*)d_in[2];
    const float* Ua     = (const float*)d_in[3];
    const float* Ub     = (const float*)d_in[4];
    const float* bt     = (const float*)d_in[5];
    const float* W_ih   = (const float*)d_in[6];
    const float* b_lstm = (const float*)d_in[8];
    const float* W1     = (const float*)d_in[9];
    const float* b1     = (const float*)d_in[10];
    const float* W2     = (const float*)d_in[11];
    const float* b2     = (const float*)d_in[12];
    const float* actorW = (const float*)d_in[13];
    const float* actorb = (const float*)d_in[14];
    float* out = (float*)d_out;

    cudaFuncSetAttribute(level_mma, cudaFuncAttributeMaxDynamicSharedMemorySize, SMEM_TOTAL);
    cudaFuncSetAttribute(top_mma, cudaFuncAttributeMaxDynamicSharedMemorySize, SMEM_TOTAL);

    bprep_kernel<<<160, 256>>>(Ua, Ub);
    leaf_kernel<<<(BSZ * 2048 * 16) / 256, 256>>>(x_idx, Wx, bt);

    for (int d = 10; d >= 8; --d) {
        int ntiles = 1 << d;
        int grid = ntiles < 152 ? ntiles : 152;
        level_mma<<<grid, NT, SMEM_TOTAL>>>(d, x_idx, Wx, bt, (d + 1) & 1, d & 1);
    }
    top_mma<<<BSZ, NT, SMEM_TOTAL>>>(x_idx, Wx, bt);

    head_kernel<<<BSZ, 64>>>(W1, b1, W2, b2, W_ih, b_lstm, actorW, actorb, vm, out);
}

// round 4
// speedup vs baseline: 2.8625x; 1.5485x over previous
#include <cuda_runtime.h>
#include <cuda_bf16.h>
#include <math.h>
#include <cstdint>

#define BSZ 128
#define NTREE 4095
#define NT 512

// smem bytes: A tile (swizzled rows) 32KB @0; z stage 128x656B @32768; B frags 80KB
#define A_OFF 0
#define Z_OFF 32768
#define ZSTRIDE_B 656
#define B_OFF (32768 + 128 * 656)
#define SMEM_TOTAL (B_OFF + 81920)

__device__ __nv_bfloat16 g_h[2][(size_t)BSZ * 2048 * 64];
__device__ float g_c[2][(size_t)BSZ * 2048 * 64];
__device__ uint32_t g_Bfrag[20480];   // bf16x2 fragment-ordered U

__device__ __forceinline__ uint32_t smem_u32(const void* p) {
    uint32_t a;
    asm("{ .reg .u64 t; cvta.to.shared.u64 t, %1; cvt.u32.u64 %0, t; }" : "=r"(a) : "l"(p));
    return a;
}
__device__ __forceinline__ float tanhap(float x) {
    float y;
    asm("tanh.approx.f32 %0, %1;" : "=f"(y) : "f"(x));
    return y;
}
__device__ __forceinline__ float sigap(float x) {
    return fmaf(tanhap(0.5f * x), 0.5f, 0.5f);
}
__device__ __forceinline__ uint32_t pbf2(float lo, float hi) {
    uint32_t r;
    asm("cvt.rn.bf16x2.f32 %0, %1, %2;" : "=r"(r) : "f"(hi), "f"(lo));
    return r;
}
__device__ __forceinline__ void ubf2(uint32_t p, float& lo, float& hi) {
    __nv_bfloat162 b = *(__nv_bfloat162*)&p;
    lo = __bfloat162float(b.x);
    hi = __bfloat162float(b.y);
}
__device__ __forceinline__ void mma_bf16(float c[4], uint32_t a0, uint32_t a1,
                                         uint32_t a2, uint32_t a3,
                                         uint32_t b0, uint32_t b1) {
    asm volatile(
        "mma.sync.aligned.m16n8k16.row.col.f32.bf16.bf16.f32 "
        "{%0,%1,%2,%3}, {%4,%5,%6,%7}, {%8,%9}, {%0,%1,%2,%3};"
        : "+f"(c[0]), "+f"(c[1]), "+f"(c[2]), "+f"(c[3])
        : "r"(a0), "r"(a1), "r"(a2), "r"(a3), "r"(b0), "r"(b1));
}

// ---------------- B fragment prep: [g][wn][ks][lane][j] bf16x2, j=0 -> k, j=1 -> k+8
__global__ void bprep_kernel(const float* __restrict__ Ua, const float* __restrict__ Ub) {
    int id = blockIdx.x * blockDim.x + threadIdx.x;   // 20480
    if (id >= 20480) return;
    int j = id & 1;
    int lane = (id >> 1) & 31;
    int ks = (id >> 6) & 7;
    int wn = (id >> 9) & 7;
    int g = id >> 12;
    int k0 = ks * 16 + (lane & 3) * 2 + j * 8;
    int n = g * 64 + wn * 8 + (lane >> 2);
    float v0 = (k0 < 64) ? Ua[k0 * 320 + n] : Ub[(k0 - 64) * 320 + n];
    float v1 = (k0 + 1 < 64) ? Ua[(k0 + 1) * 320 + n] : Ub[(k0 + 1 - 64) * 320 + n];
    g_Bfrag[id] = pbf2(v0, v1);
}

// ---------------- leaf level d=11
__global__ void leaf_kernel(const int* __restrict__ x_idx,
                            const float* __restrict__ Wx,
                            const float* __restrict__ bt) {
    int id = blockIdx.x * blockDim.x + threadIdx.x;   // B*2048*16
    int q = id & 15;
    int m = id >> 4;
    int b = m >> 11, jl = m & 2047;
    int idx = x_idx[b * NTREE + 2047 + jl];
    const float* w = Wx + idx * 320;
    int c4 = q * 4;
    float4 wi = *(const float4*)(w + c4),       bi = *(const float4*)(bt + c4);
    float4 wo = *(const float4*)(w + 192 + c4), bo = *(const float4*)(bt + 192 + c4);
    float4 wu = *(const float4*)(w + 256 + c4), bu = *(const float4*)(bt + 256 + c4);
    float zi[4] = {wi.x + bi.x, wi.y + bi.y, wi.z + bi.z, wi.w + bi.w};
    float zo[4] = {wo.x + bo.x, wo.y + bo.y, wo.z + bo.z, wo.w + bo.w};
    float zu[4] = {wu.x + bu.x, wu.y + bu.y, wu.z + bu.z, wu.w + bu.w};
    float cv[4], hv[4];
#pragma unroll
    for (int e = 0; e < 4; ++e) {
        cv[e] = sigap(zi[e]) * tanhap(zu[e]);
        hv[e] = sigap(zo[e]) * tanhap(cv[e]);
    }
    *(uint2*)(g_h[1] + (size_t)m * 64 + c4) = make_uint2(pbf2(hv[0], hv[1]), pbf2(hv[2], hv[3]));
    *(float4*)(g_c[1] + (size_t)m * 64 + c4) = make_float4(cv[0], cv[1], cv[2], cv[3]);
}

// ---------------- tile pieces
__device__ __forceinline__ void fill_a(char* smem, const __nv_bfloat16* __restrict__ asrc,
                                       int nvalid) {
    int tid = threadIdx.x;
    const uint4* src = (const uint4*)asrc;     // 16B chunks: row = f>>4, chunk = f&15
#pragma unroll
    for (int i = 0; i < 4; ++i) {
        int f = tid + i * NT;
        int row = f >> 4, c = f & 15;
        uint4 v = make_uint4(0, 0, 0, 0);
        if (row < nvalid) v = src[f];
        *(uint4*)(smem + A_OFF + row * 256 + ((c ^ (row & 7)) << 4)) = v;
    }
}

__device__ __forceinline__ void do_mma(char* smem, uint32_t sA, float acc[4][5][4],
                                       int nvalid, int wm, int wn, int lane) {
    const int row_local = (lane & 7) | (((lane >> 3) & 1) << 3);
    const int hi = (lane >> 4) & 1;
#pragma unroll
    for (int ks = 0; ks < 8; ++ks) {
        uint2 bf[5];
#pragma unroll
        for (int g = 0; g < 5; ++g)
            bf[g] = *(const uint2*)(smem + B_OFF + ((((g * 8 + wn) * 8 + ks) * 32 + lane) << 3));
        int c = ks * 2 + hi;
#pragma unroll
        for (int mfl = 0; mfl < 4; ++mfl) {
            int mf = wm * 4 + mfl;
            if (mf * 16 < nvalid) {
                uint32_t addr = sA + (mf * 16 + row_local) * 256 + ((c ^ (lane & 7)) << 4);
                uint32_t a0, a1, a2, a3;
                asm volatile("ldmatrix.sync.aligned.m8n8.x4.shared.b16 {%0,%1,%2,%3}, [%4];"
                             : "=r"(a0), "=r"(a1), "=r"(a2), "=r"(a3) : "r"(addr));
#pragma unroll
                for (int g = 0; g < 5; ++g)
                    mma_bf16(acc[mfl][g], a0, a1, a2, a3, bf[g].x, bf[g].y);
            }
        }
    }
}

__device__ __forceinline__ void stz(char* smem, float acc[4][5][4], int nvalid,
                                    int wm, int wn, int lane) {
    int colb = wn * 16 + (lane & 3) * 4;
#pragma unroll
    for (int mfl = 0; mfl < 4; ++mfl) {
        int mf = wm * 4 + mfl;
        if (mf * 16 < nvalid) {
            int row = mf * 16 + (lane >> 2);
#pragma unroll
            for (int g = 0; g < 5; ++g) {
                *(uint32_t*)(smem + Z_OFF + row * ZSTRIDE_B + g * 128 + colb) =
                    pbf2(acc[mfl][g][0], acc[mfl][g][1]);
                *(uint32_t*)(smem + Z_OFF + (row + 8) * ZSTRIDE_B + g * 128 + colb) =
                    pbf2(acc[mfl][g][2], acc[mfl][g][3]);
            }
        }
    }
}

__device__ __forceinline__ void epilogue(char* smem, int nvalid, const int* __restrict__ idxp,
                                         const float* __restrict__ csrc,
                                         __nv_bfloat16* __restrict__ houtp,
                                         float* __restrict__ coutp,
                                         const float* __restrict__ Wx,
                                         const float2 barr[5], int wid, int lane) {
#pragma unroll
    for (int rr = 0; rr < 8; ++rr) {
        int row = wid * 8 + rr;
        if (row < nvalid) {
            int idx = idxp[row];
            const float* w = Wx + idx * 320 + 2 * lane;
            float z[5][2];
#pragma unroll
            for (int g = 0; g < 5; ++g) {
                uint32_t p = *(uint32_t*)(smem + Z_OFF + row * ZSTRIDE_B + g * 128 + lane * 4);
                ubf2(p, z[g][0], z[g][1]);
            }
            float2 wv[5];
#pragma unroll
            for (int g = 0; g < 5; ++g) wv[g] = *(const float2*)(w + g * 64);
            const float* crow = csrc + (size_t)row * 128 + 2 * lane;
            float2 ca = *(const float2*)crow;
            float2 cb = *(const float2*)(crow + 64);
            float zi0 = z[0][0] + wv[0].x + barr[0].x, zi1 = z[0][1] + wv[0].y + barr[0].y;
            float za0 = z[1][0] + wv[1].x + barr[1].x, za1 = z[1][1] + wv[1].y + barr[1].y;
            float zb0 = z[2][0] + wv[2].x + barr[2].x, zb1 = z[2][1] + wv[2].y + barr[2].y;
            float zo0 = z[3][0] + wv[3].x + barr[3].x, zo1 = z[3][1] + wv[3].y + barr[3].y;
            float zu0 = z[4][0] + wv[4].x + barr[4].x, zu1 = z[4][1] + wv[4].y + barr[4].y;
            float c0 = sigap(zi0) * tanhap(zu0) + sigap(za0) * ca.x + sigap(zb0) * cb.x;
            float c1 = sigap(zi1) * tanhap(zu1) + sigap(za1) * ca.y + sigap(zb1) * cb.y;
            float h0 = sigap(zo0) * tanhap(c0);
            float h1 = sigap(zo1) * tanhap(c1);
            *(uint32_t*)(houtp + (size_t)row * 64 + 2 * lane) = pbf2(h0, h1);
            *(float2*)(coutp + (size_t)row * 64 + 2 * lane) = make_float2(c0, c1);
        }
    }
}

__device__ __forceinline__ void load_common(char* smem, const float* bt, float2 barr[5]) {
    int tid = threadIdx.x;
    const uint4* src = (const uint4*)g_Bfrag;
    uint4* dst = (uint4*)(smem + B_OFF);
#pragma unroll
    for (int i = 0; i < 10; ++i) dst[tid + i * NT] = src[tid + i * NT];
    int lane = tid & 31;
#pragma unroll
    for (int g = 0; g < 5; ++g) barr[g] = *(const float2*)(bt + g * 64 + 2 * lane);
}

// ---------------- big levels d = 10, 9, 8 (pipelined: epilogue overlaps next A-fill)
__global__ void __launch_bounds__(NT, 1)
level_mma(int d, const int* __restrict__ x_idx, const float* __restrict__ Wx,
          const float* __restrict__ bt, int pin, int pout) {
    extern __shared__ char smem[];
    uint32_t sA = smem_u32(smem) + A_OFF;
    float2 barr[5];
    load_common(smem, bt, barr);
    int lane = threadIdx.x & 31, wid = threadIdx.x >> 5;
    int wm = wid >> 3, wn = wid & 7;
    const __nv_bfloat16* hc = g_h[pin];
    const float* cc = g_c[pin];
    __nv_bfloat16* ho = g_h[pout];
    float* co = g_c[pout];
    const int n = 1 << d;
    int t = blockIdx.x;
    if (t < n) fill_a(smem, hc + (size_t)(t << 7) * 128, 128);
    __syncthreads();
    for (; t < n; t += gridDim.x) {
        int m0 = t << 7;
        float acc[4][5][4] = {};
        do_mma(smem, sA, acc, 128, wm, wn, lane);
        stz(smem, acc, 128, wm, wn, lane);
        __syncthreads();
        int b = m0 >> d, jl0 = m0 & (n - 1);
        epilogue(smem, 128, x_idx + b * NTREE + (n - 1) + jl0, cc + (size_t)m0 * 128,
                 ho + (size_t)m0 * 64, co + (size_t)m0 * 64, Wx, barr, wid, lane);
        int nt = t + gridDim.x;
        if (nt < n) fill_a(smem, hc + (size_t)(nt << 7) * 128, 128);
        __syncthreads();
    }
}

// ---------------- fused top levels d = 7..0, one CTA per batch
__global__ void __launch_bounds__(NT, 1)
top_mma(const int* __restrict__ x_idx, const float* __restrict__ Wx,
        const float* __restrict__ bt) {
    extern __shared__ char smem[];
    uint32_t sA = smem_u32(smem) + A_OFF;
    float2 barr[5];
    load_common(smem, bt, barr);
    int lane = threadIdx.x & 31, wid = threadIdx.x >> 5;
    int wm = wid >> 3, wn = wid & 7;
    int b = blockIdx.x;
    for (int d = 7; d >= 0; --d) {
        int n = 1 << d;
        int pin = (d + 1) & 1, pout = d & 1;
        fill_a(smem, g_h[pin] + (size_t)b * (2 * n) * 64, n);
        __syncthreads();
        float acc[4][5][4] = {};
        do_mma(smem, sA, acc, n, wm, wn, lane);
        stz(smem, acc, n, wm, wn, lane);
        __syncthreads();
        epilogue(smem, n, x_idx + b * NTREE + (n - 1), g_c[pin] + (size_t)b * 2 * n * 64,
                 g_h[pout] + (size_t)b * n * 64, g_c[pout] + (size_t)b * n * 64,
                 Wx, barr, wid, lane);
        __syncthreads();
    }
}

// ---------------- head
__global__ void head_kernel(const float* __restrict__ W1, const float* __restrict__ b1,
                            const float* __restrict__ W2, const float* __restrict__ b2,
                            const float* __restrict__ W_ih, const float* __restrict__ b_lstm,
                            const float* __restrict__ actorW, const float* __restrict__ actorb,
                            const float* __restrict__ vm, float* __restrict__ out) {
    __shared__ float sh[64], sf1[64], sfeat[128], slog[20], sinv[1];
    int b = blockIdx.x;
    int t = threadIdx.x;
    sh[t] = __bfloat162float(g_h[0][b * 64 + t]);
    __syncthreads();
    float a = 0.f;
    for (int k = 0; k < 64; ++k) a += sh[k] * W1[k * 64 + t];
    a += b1[t];
    sf1[t] = fmaxf(a, 0.f);
    __syncthreads();
    float f = 0.f;
    for (int k = 0; k < 64; ++k) f += sf1[k] * W2[k * 64 + t];
    f += b2[t];
    sfeat[t] = f;
    __syncthreads();
    float gi = 0.f, gg = 0.f, go = 0.f;
    for (int k = 0; k < 64; ++k) {
        float fk = sfeat[k];
        gi += fk * W_ih[k * 256 + t];
        gg += fk * W_ih[k * 256 + 128 + t];
        go += fk * W_ih[k * 256 + 192 + t];
    }
    gi += b_lstm[t];
    gg += b_lstm[128 + t];
    go += b_lstm[192 + t];
    float cg = (1.f / (1.f + expf(-gi))) * tanhf(gg);
    float hg = (1.f / (1.f + expf(-go))) * tanhf(cg);
    sfeat[64 + t] = hg;
    __syncthreads();
    if (t < 20) {
        float l = 0.f;
        for (int dd = 0; dd < 128; ++dd) l += sfeat[dd] * actorW[dd * 20 + t];
        l = logf(vm[t]) + l * vm[t] + actorb[t] * vm[t];
        slog[t] = l / 3.0f;
    }
    __syncthreads();
    if (t == 0) {
        float mx = slog[0];
        for (int k = 1; k < 20; ++k) mx = fmaxf(mx, slog[k]);
        float s = 0.f;
        for (int k = 0; k < 20; ++k) {
            float e = expf(slog[k] - mx);
            slog[k] = e;
            s += e;
        }
        sinv[0] = 1.f / s;
    }
    __syncthreads();
    if (t < 20) out[b * 20 + t] = slog[t] * sinv[0];
}

extern "C" void kernel_launch(void* const* d_in, const int* in_sizes, int n_in,
                              void* d_out, int out_size) {
    const int*   x_idx  = (const int*)d_in[0];
    const float* vm     = (const float*)d_in[1];
    const float* Wx     = (const float*)d_in[2];
    const float* Ua     = (const float*)d_in[3];
    const float* Ub     = (const float*)d_in[4];
    const float* bt     = (const float*)d_in[5];
    const float* W_ih   = (const float*)d_in[6];
    const float* b_lstm = (const float*)d_in[8];
    const float* W1     = (const float*)d_in[9];
    const float* b1     = (const float*)d_in[10];
    const float* W2     = (const float*)d_in[11];
    const float* b2     = (const float*)d_in[12];
    const float* actorW = (const float*)d_in[13];
    const float* actorb = (const float*)d_in[14];
    float* out = (float*)d_out;

    cudaFuncSetAttribute(level_mma, cudaFuncAttributeMaxDynamicSharedMemorySize, SMEM_TOTAL);
    cudaFuncSetAttribute(top_mma, cudaFuncAttributeMaxDynamicSharedMemorySize, SMEM_TOTAL);

    bprep_kernel<<<80, 256>>>(Ua, Ub);
    leaf_kernel<<<(BSZ * 2048 * 16) / 256, 256>>>(x_idx, Wx, bt);

    for (int d = 10; d >= 8; --d) {
        int ntiles = 1 << d;
        int grid = ntiles < 152 ? ntiles : 152;
        level_mma<<<grid, NT, SMEM_TOTAL>>>(d, x_idx, Wx, bt, (d + 1) & 1, d & 1);
    }
    top_mma<<<BSZ, NT, SMEM_TOTAL>>>(x_idx, Wx, bt);

    head_kernel<<<BSZ, 64>>>(W1, b1, W2, b2, W_ih, b_lstm, actorW, actorb, vm, out);
}

// round 5
// speedup vs baseline: 4.1463x; 1.4485x over previous
#include <cuda_runtime.h>
#include <cuda_bf16.h>
#include <math.h>
#include <cstdint>

#define BSZ 128
#define NTREE 4095
#define NT 512

// smem bytes: A ping-pong 2x32KB @0; z stage 128x656B @65536; B frags 80KB
#define A_OFF 0
#define Z_OFF 65536
#define ZSTRIDE_B 656
#define B_OFF (Z_OFF + 128 * ZSTRIDE_B)
#define SMEM_TOTAL (B_OFF + 81920)

__device__ __nv_bfloat16 g_h[2][(size_t)BSZ * 2048 * 64];
__device__ __nv_bfloat16 g_c[2][(size_t)BSZ * 2048 * 64];
__device__ uint32_t g_Bfrag[20480];   // bf16x2 fragment-ordered U

__device__ __forceinline__ uint32_t smem_u32(const void* p) {
    uint32_t a;
    asm("{ .reg .u64 t; cvta.to.shared.u64 t, %1; cvt.u32.u64 %0, t; }" : "=r"(a) : "l"(p));
    return a;
}
__device__ __forceinline__ float tanhap(float x) {
    float y;
    asm("tanh.approx.f32 %0, %1;" : "=f"(y) : "f"(x));
    return y;
}
__device__ __forceinline__ float sigap(float x) {
    return fmaf(tanhap(0.5f * x), 0.5f, 0.5f);
}
__device__ __forceinline__ uint32_t pbf2(float lo, float hi) {
    uint32_t r;
    asm("cvt.rn.bf16x2.f32 %0, %1, %2;" : "=r"(r) : "f"(hi), "f"(lo));
    return r;
}
__device__ __forceinline__ void ubf2(uint32_t p, float& lo, float& hi) {
    __nv_bfloat162 b = *(__nv_bfloat162*)&p;
    lo = __bfloat162float(b.x);
    hi = __bfloat162float(b.y);
}
__device__ __forceinline__ void mma_bf16(float c[4], uint32_t a0, uint32_t a1,
                                         uint32_t a2, uint32_t a3,
                                         uint32_t b0, uint32_t b1) {
    asm volatile(
        "mma.sync.aligned.m16n8k16.row.col.f32.bf16.bf16.f32 "
        "{%0,%1,%2,%3}, {%4,%5,%6,%7}, {%8,%9}, {%0,%1,%2,%3};"
        : "+f"(c[0]), "+f"(c[1]), "+f"(c[2]), "+f"(c[3])
        : "r"(a0), "r"(a1), "r"(a2), "r"(a3), "r"(b0), "r"(b1));
}

// ---------------- B fragment prep: [g][wn][ks][lane][j] bf16x2
__global__ void bprep_kernel(const float* __restrict__ Ua, const float* __restrict__ Ub) {
    int id = blockIdx.x * blockDim.x + threadIdx.x;   // 20480
    if (id >= 20480) return;
    int j = id & 1;
    int lane = (id >> 1) & 31;
    int ks = (id >> 6) & 7;
    int wn = (id >> 9) & 7;
    int g = id >> 12;
    int k0 = ks * 16 + (lane & 3) * 2 + j * 8;
    int n = g * 64 + wn * 8 + (lane >> 2);
    float v0 = (k0 < 64) ? Ua[k0 * 320 + n] : Ub[(k0 - 64) * 320 + n];
    float v1 = (k0 + 1 < 64) ? Ua[(k0 + 1) * 320 + n] : Ub[(k0 + 1 - 64) * 320 + n];
    g_Bfrag[id] = pbf2(v0, v1);
}

// ---------------- leaf level d=11
__global__ void leaf_kernel(const int* __restrict__ x_idx,
                            const float* __restrict__ Wx,
                            const float* __restrict__ bt) {
    int id = blockIdx.x * blockDim.x + threadIdx.x;   // B*2048*16
    int q = id & 15;
    int m = id >> 4;
    int b = m >> 11, jl = m & 2047;
    int idx = x_idx[b * NTREE + 2047 + jl];
    const float* w = Wx + idx * 320;
    int c4 = q * 4;
    float4 wi = *(const float4*)(w + c4),       bi = *(const float4*)(bt + c4);
    float4 wo = *(const float4*)(w + 192 + c4), bo = *(const float4*)(bt + 192 + c4);
    float4 wu = *(const float4*)(w + 256 + c4), bu = *(const float4*)(bt + 256 + c4);
    float zi[4] = {wi.x + bi.x, wi.y + bi.y, wi.z + bi.z, wi.w + bi.w};
    float zo[4] = {wo.x + bo.x, wo.y + bo.y, wo.z + bo.z, wo.w + bo.w};
    float zu[4] = {wu.x + bu.x, wu.y + bu.y, wu.z + bu.z, wu.w + bu.w};
    float cv[4], hv[4];
#pragma unroll
    for (int e = 0; e < 4; ++e) {
        cv[e] = sigap(zi[e]) * tanhap(zu[e]);
        hv[e] = sigap(zo[e]) * tanhap(cv[e]);
    }
    *(uint2*)(g_h[1] + (size_t)m * 64 + c4) = make_uint2(pbf2(hv[0], hv[1]), pbf2(hv[2], hv[3]));
    *(uint2*)(g_c[1] + (size_t)m * 64 + c4) = make_uint2(pbf2(cv[0], cv[1]), pbf2(cv[2], cv[3]));
}

// ---------------- tile pieces
__device__ __forceinline__ void fill_a(char* smem, const __nv_bfloat16* __restrict__ asrc,
                                       int nvalid) {
    int tid = threadIdx.x;
    const uint4* src = (const uint4*)asrc;
#pragma unroll
    for (int i = 0; i < 4; ++i) {
        int f = tid + i * NT;
        int row = f >> 4, c = f & 15;
        uint4 v = make_uint4(0, 0, 0, 0);
        if (row < nvalid) v = src[f];
        *(uint4*)(smem + row * 256 + ((c ^ (row & 7)) << 4)) = v;
    }
}

__device__ __forceinline__ void do_mma(char* smem, uint32_t sA, float acc[4][5][4],
                                       int nvalid, int wm, int wn, int lane) {
    const int row_local = (lane & 7) | (((lane >> 3) & 1) << 3);
    const int hi = (lane >> 4) & 1;
#pragma unroll
    for (int ks = 0; ks < 8; ++ks) {
        uint2 bf[5];
#pragma unroll
        for (int g = 0; g < 5; ++g)
            bf[g] = *(const uint2*)(smem + B_OFF + ((((g * 8 + wn) * 8 + ks) * 32 + lane) << 3));
        int c = ks * 2 + hi;
#pragma unroll
        for (int mfl = 0; mfl < 4; ++mfl) {
            int mf = wm * 4 + mfl;
            if (mf * 16 < nvalid) {
                uint32_t addr = sA + (mf * 16 + row_local) * 256 + ((c ^ (lane & 7)) << 4);
                uint32_t a0, a1, a2, a3;
                asm volatile("ldmatrix.sync.aligned.m8n8.x4.shared.b16 {%0,%1,%2,%3}, [%4];"
                             : "=r"(a0), "=r"(a1), "=r"(a2), "=r"(a3) : "r"(addr));
#pragma unroll
                for (int g = 0; g < 5; ++g)
                    mma_bf16(acc[mfl][g], a0, a1, a2, a3, bf[g].x, bf[g].y);
            }
        }
    }
}

// z staging via stmatrix: packed accs are exactly the stmatrix fragment source
__device__ __forceinline__ void stz(uint32_t sb, float acc[4][5][4],
                                    int wm, int wn, int lane) {
    int mat = lane >> 3, i = lane & 7;
#pragma unroll
    for (int g = 0; g < 5; ++g) {
#pragma unroll
        for (int M0 = 0; M0 < 4; M0 += 2) {
            int row = wm * 64 + (M0 + (mat >> 1)) * 16 + (mat & 1) * 8 + i;
            uint32_t addr = sb + Z_OFF + row * ZSTRIDE_B + g * 128 + wn * 16;
            uint32_t r0 = pbf2(acc[M0][g][0], acc[M0][g][1]);
            uint32_t r1 = pbf2(acc[M0][g][2], acc[M0][g][3]);
            uint32_t r2 = pbf2(acc[M0 + 1][g][0], acc[M0 + 1][g][1]);
            uint32_t r3 = pbf2(acc[M0 + 1][g][2], acc[M0 + 1][g][3]);
            asm volatile("stmatrix.sync.aligned.m8n8.x4.shared.b16 [%0], {%1,%2,%3,%4};"
                         :: "r"(addr), "r"(r0), "r"(r1), "r"(r2), "r"(r3));
        }
    }
}

__device__ __forceinline__ void epilogue(char* smem, int nvalid, const int* __restrict__ idxp,
                                         const __nv_bfloat16* __restrict__ csrc,
                                         __nv_bfloat16* __restrict__ houtp,
                                         __nv_bfloat16* __restrict__ coutp,
                                         const float* __restrict__ Wx,
                                         const float2 barr[5], int wid, int lane) {
#pragma unroll
    for (int rr = 0; rr < 8; ++rr) {
        int row = wid * 8 + rr;
        if (row < nvalid) {
            int idx = idxp[row];
            const float* w = Wx + idx * 320 + 2 * lane;
            float z[5][2];
#pragma unroll
            for (int g = 0; g < 5; ++g) {
                uint32_t p = *(uint32_t*)(smem + Z_OFF + row * ZSTRIDE_B + g * 128 + lane * 4);
                ubf2(p, z[g][0], z[g][1]);
            }
            float2 wv[5];
#pragma unroll
            for (int g = 0; g < 5; ++g) wv[g] = *(const float2*)(w + g * 64);
            const __nv_bfloat16* crow = csrc + (size_t)row * 128 + 2 * lane;
            float ca0, ca1, cb0, cb1;
            ubf2(*(const uint32_t*)crow, ca0, ca1);
            ubf2(*(const uint32_t*)(crow + 64), cb0, cb1);
            float zi0 = z[0][0] + wv[0].x + barr[0].x, zi1 = z[0][1] + wv[0].y + barr[0].y;
            float za0 = z[1][0] + wv[1].x + barr[1].x, za1 = z[1][1] + wv[1].y + barr[1].y;
            float zb0 = z[2][0] + wv[2].x + barr[2].x, zb1 = z[2][1] + wv[2].y + barr[2].y;
            float zo0 = z[3][0] + wv[3].x + barr[3].x, zo1 = z[3][1] + wv[3].y + barr[3].y;
            float zu0 = z[4][0] + wv[4].x + barr[4].x, zu1 = z[4][1] + wv[4].y + barr[4].y;
            float c0 = sigap(zi0) * tanhap(zu0) + sigap(za0) * ca0 + sigap(zb0) * cb0;
            float c1 = sigap(zi1) * tanhap(zu1) + sigap(za1) * ca1 + sigap(zb1) * cb1;
            float h0 = sigap(zo0) * tanhap(c0);
            float h1 = sigap(zo1) * tanhap(c1);
            *(uint32_t*)(houtp + (size_t)row * 64 + 2 * lane) = pbf2(h0, h1);
            *(uint32_t*)(coutp + (size_t)row * 64 + 2 * lane) = pbf2(c0, c1);
        }
    }
}

__device__ __forceinline__ void load_common(char* smem, const float* bt, float2 barr[5]) {
    int tid = threadIdx.x;
    const uint4* src = (const uint4*)g_Bfrag;
    uint4* dst = (uint4*)(smem + B_OFF);
#pragma unroll
    for (int i = 0; i < 10; ++i) dst[tid + i * NT] = src[tid + i * NT];
    int lane = tid & 31;
#pragma unroll
    for (int g = 0; g < 5; ++g) barr[g] = *(const float2*)(bt + g * 64 + 2 * lane);
}

// ---------------- big levels d = 10, 9, 8 (double-buffered A)
__global__ void __launch_bounds__(NT, 1)
level_mma(int d, const int* __restrict__ x_idx, const float* __restrict__ Wx,
          const float* __restrict__ bt, int pin, int pout) {
    extern __shared__ char smem[];
    uint32_t sb = smem_u32(smem);
    float2 barr[5];
    load_common(smem, bt, barr);
    int lane = threadIdx.x & 31, wid = threadIdx.x >> 5;
    int wm = wid >> 3, wn = wid & 7;
    const __nv_bfloat16* hc = g_h[pin];
    const __nv_bfloat16* cc = g_c[pin];
    __nv_bfloat16* ho = g_h[pout];
    __nv_bfloat16* co = g_c[pout];
    const int n = 1 << d;
    int t = blockIdx.x;
    int p = 0;
    if (t < n) fill_a(smem, hc + (size_t)(t << 7) * 128, 128);
    __syncthreads();
    for (; t < n; t += gridDim.x) {
        int m0 = t << 7;
        float acc[4][5][4] = {};
        do_mma(smem, sb + p * 32768, acc, 128, wm, wn, lane);
        int nt = t + gridDim.x;
        if (nt < n) fill_a(smem + (p ^ 1) * 32768, hc + (size_t)(nt << 7) * 128, 128);
        stz(sb, acc, wm, wn, lane);
        __syncthreads();
        int b = m0 >> d, jl0 = m0 & (n - 1);
        epilogue(smem, 128, x_idx + b * NTREE + (n - 1) + jl0, cc + (size_t)m0 * 128,
                 ho + (size_t)m0 * 64, co + (size_t)m0 * 64, Wx, barr, wid, lane);
        p ^= 1;
        __syncthreads();
    }
}

// ---------------- fused top levels d = 7..0, one CTA per batch
__global__ void __launch_bounds__(NT, 1)
top_mma(const int* __restrict__ x_idx, const float* __restrict__ Wx,
        const float* __restrict__ bt) {
    extern __shared__ char smem[];
    uint32_t sb = smem_u32(smem);
    float2 barr[5];
    load_common(smem, bt, barr);
    int lane = threadIdx.x & 31, wid = threadIdx.x >> 5;
    int wm = wid >> 3, wn = wid & 7;
    int b = blockIdx.x;
    for (int d = 7; d >= 0; --d) {
        int n = 1 << d;
        int pin = (d + 1) & 1, pout = d & 1;
        fill_a(smem, g_h[pin] + (size_t)b * (2 * n) * 64, n);
        __syncthreads();
        float acc[4][5][4] = {};
        do_mma(smem, sb, acc, n, wm, wn, lane);
        stz(sb, acc, wm, wn, lane);
        __syncthreads();
        epilogue(smem, n, x_idx + b * NTREE + (n - 1), g_c[pin] + (size_t)b * 2 * n * 64,
                 g_h[pout] + (size_t)b * n * 64, g_c[pout] + (size_t)b * n * 64,
                 Wx, barr, wid, lane);
        __syncthreads();
    }
}

// ---------------- head
__global__ void head_kernel(const float* __restrict__ W1, const float* __restrict__ b1,
                            const float* __restrict__ W2, const float* __restrict__ b2,
                            const float* __restrict__ W_ih, const float* __restrict__ b_lstm,
                            const float* __restrict__ actorW, const float* __restrict__ actorb,
                            const float* __restrict__ vm, float* __restrict__ out) {
    __shared__ float sh[64], sf1[64], sfeat[128], slog[20], sinv[1];
    int b = blockIdx.x;
    int t = threadIdx.x;
    sh[t] = __bfloat162float(g_h[0][b * 64 + t]);
    __syncthreads();
    float a = 0.f;
    for (int k = 0; k < 64; ++k) a += sh[k] * W1[k * 64 + t];
    a += b1[t];
    sf1[t] = fmaxf(a, 0.f);
    __syncthreads();
    float f = 0.f;
    for (int k = 0; k < 64; ++k) f += sf1[k] * W2[k * 64 + t];
    f += b2[t];
    sfeat[t] = f;
    __syncthreads();
    float gi = 0.f, gg = 0.f, go = 0.f;
    for (int k = 0; k < 64; ++k) {
        float fk = sfeat[k];
        gi += fk * W_ih[k * 256 + t];
        gg += fk * W_ih[k * 256 + 128 + t];
        go += fk * W_ih[k * 256 + 192 + t];
    }
    gi += b_lstm[t];
    gg += b_lstm[128 + t];
    go += b_lstm[192 + t];
    float cg = (1.f / (1.f + expf(-gi))) * tanhf(gg);
    float hg = (1.f / (1.f + expf(-go))) * tanhf(cg);
    sfeat[64 + t] = hg;
    __syncthreads();
    if (t < 20) {
        float l = 0.f;
        for (int dd = 0; dd < 128; ++dd) l += sfeat[dd] * actorW[dd * 20 + t];
        l = logf(vm[t]) + l * vm[t] + actorb[t] * vm[t];
        slog[t] = l / 3.0f;
    }
    __syncthreads();
    if (t == 0) {
        float mx = slog[0];
        for (int k = 1; k < 20; ++k) mx = fmaxf(mx, slog[k]);
        float s = 0.f;
        for (int k = 0; k < 20; ++k) {
            float e = expf(slog[k] - mx);
            slog[k] = e;
            s += e;
        }
        sinv[0] = 1.f / s;
    }
    __syncthreads();
    if (t < 20) out[b * 20 + t] = slog[t] * sinv[0];
}

extern "C" void kernel_launch(void* const* d_in, const int* in_sizes, int n_in,
                              void* d_out, int out_size) {
    const int*   x_idx  = (const int*)d_in[0];
    const float* vm     = (const float*)d_in[1];
    const float* Wx     = (const float*)d_in[2];
    const float* Ua     = (const float*)d_in[3];
    const float* Ub     = (const float*)d_in[4];
    const float* bt     = (const float*)d_in[5];
    const float* W_ih   = (const float*)d_in[6];
    const float* b_lstm = (const float*)d_in[8];
    const float* W1     = (const float*)d_in[9];
    const float* b1     = (const float*)d_in[10];
    const float* W2     = (const float*)d_in[11];
    const float* b2     = (const float*)d_in[12];
    const float* actorW = (const float*)d_in[13];
    const float* actorb = (const float*)d_in[14];
    float* out = (float*)d_out;

    cudaFuncSetAttribute(level_mma, cudaFuncAttributeMaxDynamicSharedMemorySize, SMEM_TOTAL);
    cudaFuncSetAttribute(top_mma, cudaFuncAttributeMaxDynamicSharedMemorySize, SMEM_TOTAL);

    bprep_kernel<<<80, 256>>>(Ua, Ub);
    leaf_kernel<<<(BSZ * 2048 * 16) / 256, 256>>>(x_idx, Wx, bt);

    for (int d = 10; d >= 8; --d) {
        int ntiles = 1 << d;
        int grid = ntiles < 152 ? ntiles : 152;
        level_mma<<<grid, NT, SMEM_TOTAL>>>(d, x_idx, Wx, bt, (d + 1) & 1, d & 1);
    }
    top_mma<<<BSZ, NT, SMEM_TOTAL>>>(x_idx, Wx, bt);

    head_kernel<<<BSZ, 64>>>(W1, b1, W2, b2, W_ih, b_lstm, actorW, actorb, vm, out);
}

// round 6
// speedup vs baseline: 4.4308x; 1.0686x over previous
#include <cuda_runtime.h>
#include <cuda_bf16.h>
#include <math.h>
#include <cstdint>

#define BSZ 128
#define NTREE 4095
#define NT 512

// smem bytes:
//   A group0: [0,32768) two 16KB buffers; A group1: [32768,65536)
//   Z group0 @65536, group1 @107520 (64 x 656B each)
//   B frags  @149504, 80KB  -> total 231424
#define AG(g, p) ((g) * 32768 + (p) * 16384)
#define Z_OFF 65536
#define ZG_SZ 41984
#define ZSTRIDE_B 656
#define B_OFF 149504
#define SMEM_TOTAL (B_OFF + 81920)

__device__ __nv_bfloat16 g_h[2][(size_t)BSZ * 2048 * 64];
__device__ __nv_bfloat16 g_c[2][(size_t)BSZ * 2048 * 64];
__device__ uint32_t g_Bfrag[20480];   // bf16x2 fragment-ordered U
__device__ uint32_t g_Wxb[20480];     // bf16x2 Wx table [idx][g][lane]

__device__ __forceinline__ uint32_t smem_u32(const void* p) {
    uint32_t a;
    asm("{ .reg .u64 t; cvta.to.shared.u64 t, %1; cvt.u32.u64 %0, t; }" : "=r"(a) : "l"(p));
    return a;
}
__device__ __forceinline__ float tanhap(float x) {
    float y;
    asm("tanh.approx.f32 %0, %1;" : "=f"(y) : "f"(x));
    return y;
}
__device__ __forceinline__ float sigap(float x) {
    return fmaf(tanhap(0.5f * x), 0.5f, 0.5f);
}
__device__ __forceinline__ uint32_t pbf2(float lo, float hi) {
    uint32_t r;
    asm("cvt.rn.bf16x2.f32 %0, %1, %2;" : "=r"(r) : "f"(hi), "f"(lo));
    return r;
}
__device__ __forceinline__ void ubf2(uint32_t p, float& lo, float& hi) {
    __nv_bfloat162 b = *(__nv_bfloat162*)&p;
    lo = __bfloat162float(b.x);
    hi = __bfloat162float(b.y);
}
__device__ __forceinline__ void mma_bf16(float c[4], uint32_t a0, uint32_t a1,
                                         uint32_t a2, uint32_t a3,
                                         uint32_t b0, uint32_t b1) {
    asm volatile(
        "mma.sync.aligned.m16n8k16.row.col.f32.bf16.bf16.f32 "
        "{%0,%1,%2,%3}, {%4,%5,%6,%7}, {%8,%9}, {%0,%1,%2,%3};"
        : "+f"(c[0]), "+f"(c[1]), "+f"(c[2]), "+f"(c[3])
        : "r"(a0), "r"(a1), "r"(a2), "r"(a3), "r"(b0), "r"(b1));
}
#define BARG(g) asm volatile("bar.sync %0, 256;" :: "r"((g) + 1) : "memory")

// ---------------- prep: U fragments + Wx bf16 table
__global__ void prep_kernel(const float* __restrict__ Ua, const float* __restrict__ Ub,
                            const float* __restrict__ Wx) {
    int id = blockIdx.x * blockDim.x + threadIdx.x;   // 20480
    if (id >= 20480) return;
    {   // U: [g][wn][ks][lane][j]
        int j = id & 1;
        int lane = (id >> 1) & 31;
        int ks = (id >> 6) & 7;
        int wn = (id >> 9) & 7;
        int g = id >> 12;
        int k0 = ks * 16 + (lane & 3) * 2 + j * 8;
        int n = g * 64 + wn * 8 + (lane >> 2);
        float v0 = (k0 < 64) ? Ua[k0 * 320 + n] : Ub[(k0 - 64) * 320 + n];
        float v1 = (k0 + 1 < 64) ? Ua[(k0 + 1) * 320 + n] : Ub[(k0 + 1 - 64) * 320 + n];
        g_Bfrag[id] = pbf2(v0, v1);
    }
    {   // Wx: [idx][g][lane] = cols (g*64+2l, +1)
        int idx = id / 160;
        int rem = id - idx * 160;
        int g = rem >> 5, lane = rem & 31;
        const float* w = Wx + idx * 320 + g * 64 + 2 * lane;
        g_Wxb[id] = pbf2(w[0], w[1]);
    }
}

// ---------------- leaf level d=11
__global__ void leaf_kernel(const int* __restrict__ x_idx,
                            const float* __restrict__ bt) {
    int id = blockIdx.x * blockDim.x + threadIdx.x;   // B*2048*16
    int q = id & 15;
    int m = id >> 4;
    int b = m >> 11, jl = m & 2047;
    int idx = x_idx[b * NTREE + 2047 + jl];
    const uint32_t* w = g_Wxb + idx * 160 + q * 2;
    int c4 = q * 4;
    uint2 wi = *(const uint2*)(w);
    uint2 wo = *(const uint2*)(w + 96);
    uint2 wu = *(const uint2*)(w + 128);
    float4 bi = *(const float4*)(bt + c4);
    float4 bo = *(const float4*)(bt + 192 + c4);
    float4 bu = *(const float4*)(bt + 256 + c4);
    float wif[4], wof[4], wuf[4];
    ubf2(wi.x, wif[0], wif[1]); ubf2(wi.y, wif[2], wif[3]);
    ubf2(wo.x, wof[0], wof[1]); ubf2(wo.y, wof[2], wof[3]);
    ubf2(wu.x, wuf[0], wuf[1]); ubf2(wu.y, wuf[2], wuf[3]);
    float zi[4] = {wif[0] + bi.x, wif[1] + bi.y, wif[2] + bi.z, wif[3] + bi.w};
    float zo[4] = {wof[0] + bo.x, wof[1] + bo.y, wof[2] + bo.z, wof[3] + bo.w};
    float zu[4] = {wuf[0] + bu.x, wuf[1] + bu.y, wuf[2] + bu.z, wuf[3] + bu.w};
    float cv[4], hv[4];
#pragma unroll
    for (int e = 0; e < 4; ++e) {
        cv[e] = sigap(zi[e]) * tanhap(zu[e]);
        hv[e] = sigap(zo[e]) * tanhap(cv[e]);
    }
    *(uint2*)(g_h[1] + (size_t)m * 64 + c4) = make_uint2(pbf2(hv[0], hv[1]), pbf2(hv[2], hv[3]));
    *(uint2*)(g_c[1] + (size_t)m * 64 + c4) = make_uint2(pbf2(cv[0], cv[1]), pbf2(cv[2], cv[3]));
}

// ---------------- 64-row group-tile pieces (8 warps, 256 threads per group)
__device__ __forceinline__ void fill_a64(char* smem, int abase,
                                         const __nv_bfloat16* __restrict__ asrc,
                                         int nvalid, int tidl) {
    const uint4* src = (const uint4*)asrc;
#pragma unroll
    for (int i = 0; i < 4; ++i) {
        int f = tidl + i * 256;           // 0..1023
        int row = f >> 4, c = f & 15;
        uint4 v = make_uint4(0, 0, 0, 0);
        if (row < nvalid) v = src[f];
        *(uint4*)(smem + abase + row * 256 + ((c ^ (row & 7)) << 4)) = v;
    }
}

__device__ __forceinline__ void do_mma64(char* smem, uint32_t sA, float acc[4][5][4],
                                         int nvalid, int wl, int lane) {
    const int row_local = (lane & 7) | (((lane >> 3) & 1) << 3);
    const int hi = (lane >> 4) & 1;
#pragma unroll
    for (int ks = 0; ks < 8; ++ks) {
        uint2 bf[5];
#pragma unroll
        for (int g = 0; g < 5; ++g)
            bf[g] = *(const uint2*)(smem + B_OFF + ((((g * 8 + wl) * 8 + ks) * 32 + lane) << 3));
        int c = ks * 2 + hi;
#pragma unroll
        for (int mfl = 0; mfl < 4; ++mfl) {
            if (mfl * 16 < nvalid) {
                uint32_t addr = sA + (mfl * 16 + row_local) * 256 + ((c ^ (lane & 7)) << 4);
                uint32_t a0, a1, a2, a3;
                asm volatile("ldmatrix.sync.aligned.m8n8.x4.shared.b16 {%0,%1,%2,%3}, [%4];"
                             : "=r"(a0), "=r"(a1), "=r"(a2), "=r"(a3) : "r"(addr));
#pragma unroll
                for (int g = 0; g < 5; ++g)
                    mma_bf16(acc[mfl][g], a0, a1, a2, a3, bf[g].x, bf[g].y);
            }
        }
    }
}

__device__ __forceinline__ void stz64(uint32_t sb, int zbase, float acc[4][5][4],
                                      int wl, int lane) {
    int mat = lane >> 3, i = lane & 7;
#pragma unroll
    for (int g = 0; g < 5; ++g) {
#pragma unroll
        for (int M0 = 0; M0 < 4; M0 += 2) {
            int row = (M0 + (mat >> 1)) * 16 + (mat & 1) * 8 + i;
            uint32_t addr = sb + zbase + row * ZSTRIDE_B + g * 128 + wl * 16;
            uint32_t r0 = pbf2(acc[M0][g][0], acc[M0][g][1]);
            uint32_t r1 = pbf2(acc[M0][g][2], acc[M0][g][3]);
            uint32_t r2 = pbf2(acc[M0 + 1][g][0], acc[M0 + 1][g][1]);
            uint32_t r3 = pbf2(acc[M0 + 1][g][2], acc[M0 + 1][g][3]);
            asm volatile("stmatrix.sync.aligned.m8n8.x4.shared.b16 [%0], {%1,%2,%3,%4};"
                         :: "r"(addr), "r"(r0), "r"(r1), "r"(r2), "r"(r3));
        }
    }
}

__device__ __forceinline__ void epilogue64(char* smem, int zbase, int nvalid,
                                           const int* __restrict__ idxp,
                                           const __nv_bfloat16* __restrict__ csrc,
                                           __nv_bfloat16* __restrict__ houtp,
                                           __nv_bfloat16* __restrict__ coutp,
                                           const float2 barr[5], int wl, int lane) {
    int idxv[8];
#pragma unroll
    for (int rr = 0; rr < 8; ++rr) {
        int row = wl * 8 + rr;
        idxv[rr] = (row < nvalid) ? idxp[row] : 0;
    }
#pragma unroll
    for (int rr = 0; rr < 8; ++rr) {
        int row = wl * 8 + rr;
        if (row < nvalid) {
            const uint32_t* w = g_Wxb + idxv[rr] * 160 + lane;
            float z[5][2], wx[5][2];
#pragma unroll
            for (int g = 0; g < 5; ++g) {
                ubf2(*(uint32_t*)(smem + zbase + row * ZSTRIDE_B + g * 128 + lane * 4),
                     z[g][0], z[g][1]);
                ubf2(w[g * 32], wx[g][0], wx[g][1]);
            }
            const __nv_bfloat16* crow = csrc + (size_t)row * 128 + 2 * lane;
            float ca0, ca1, cb0, cb1;
            ubf2(*(const uint32_t*)crow, ca0, ca1);
            ubf2(*(const uint32_t*)(crow + 64), cb0, cb1);
            float zi0 = z[0][0] + wx[0][0] + barr[0].x, zi1 = z[0][1] + wx[0][1] + barr[0].y;
            float za0 = z[1][0] + wx[1][0] + barr[1].x, za1 = z[1][1] + wx[1][1] + barr[1].y;
            float zb0 = z[2][0] + wx[2][0] + barr[2].x, zb1 = z[2][1] + wx[2][1] + barr[2].y;
            float zo0 = z[3][0] + wx[3][0] + barr[3].x, zo1 = z[3][1] + wx[3][1] + barr[3].y;
            float zu0 = z[4][0] + wx[4][0] + barr[4].x, zu1 = z[4][1] + wx[4][1] + barr[4].y;
            float c0 = sigap(zi0) * tanhap(zu0) + sigap(za0) * ca0 + sigap(zb0) * cb0;
            float c1 = sigap(zi1) * tanhap(zu1) + sigap(za1) * ca1 + sigap(zb1) * cb1;
            float h0 = sigap(zo0) * tanhap(c0);
            float h1 = sigap(zo1) * tanhap(c1);
            *(uint32_t*)(houtp + (size_t)row * 64 + 2 * lane) = pbf2(h0, h1);
            *(uint32_t*)(coutp + (size_t)row * 64 + 2 * lane) = pbf2(c0, c1);
        }
    }
}

__device__ __forceinline__ void load_common(char* smem, const float* bt, float2 barr[5]) {
    int tid = threadIdx.x;
    const uint4* src = (const uint4*)g_Bfrag;
    uint4* dst = (uint4*)(smem + B_OFF);
#pragma unroll
    for (int i = 0; i < 10; ++i) dst[tid + i * NT] = src[tid + i * NT];
    int lane = tid & 31;
#pragma unroll
    for (int g = 0; g < 5; ++g) barr[g] = *(const float2*)(bt + g * 64 + 2 * lane);
}

// ---------------- big levels d = 10, 9, 8: two phase-shifted groups per CTA
__global__ void __launch_bounds__(NT, 1)
level_mma(int d, const int* __restrict__ x_idx, const float* __restrict__ bt,
          int pin, int pout) {
    extern __shared__ char smem[];
    uint32_t sb = smem_u32(smem);
    float2 barr[5];
    load_common(smem, bt, barr);
    __syncthreads();
    const int tid = threadIdx.x;
    const int group = tid >> 8, tidl = tid & 255;
    const int wl = (tid >> 5) & 7, lane = tid & 31;
    const int zbase = Z_OFF + group * ZG_SZ;
    const __nv_bfloat16* hc = g_h[pin];
    const __nv_bfloat16* cc = g_c[pin];
    __nv_bfloat16* ho = g_h[pout];
    __nv_bfloat16* co = g_c[pout];
    const int n = 1 << d;
    const int ntile = 2 << d;              // 64-row tiles
    const int step = gridDim.x * 2;
    int t = blockIdx.x * 2 + group;
    int p = 0;
    if (t < ntile) fill_a64(smem, AG(group, 0), hc + (size_t)(t << 6) * 128, 64, tidl);
    BARG(group);
    for (; t < ntile; t += step) {
        int m0 = t << 6;
        float acc[4][5][4] = {};
        do_mma64(smem, sb + AG(group, p), acc, 64, wl, lane);
        int nt = t + step;
        if (nt < ntile)
            fill_a64(smem, AG(group, p ^ 1), hc + (size_t)(nt << 6) * 128, 64, tidl);
        stz64(sb, zbase, acc, wl, lane);
        BARG(group);
        int b = m0 >> d, jl0 = m0 & (n - 1);
        epilogue64(smem, zbase, 64, x_idx + b * NTREE + (n - 1) + jl0,
                   cc + (size_t)m0 * 128, ho + (size_t)m0 * 64, co + (size_t)m0 * 64,
                   barr, wl, lane);
        p ^= 1;
        BARG(group);
    }
}

// ---------------- fused top levels d = 7..0: rows split across groups
__global__ void __launch_bounds__(NT, 1)
top_mma(const int* __restrict__ x_idx, const float* __restrict__ bt) {
    extern __shared__ char smem[];
    uint32_t sb = smem_u32(smem);
    float2 barr[5];
    load_common(smem, bt, barr);
    __syncthreads();
    const int tid = threadIdx.x;
    const int group = tid >> 8, tidl = tid & 255;
    const int wl = (tid >> 5) & 7, lane = tid & 31;
    const int zbase = Z_OFF + group * ZG_SZ;
    const int b = blockIdx.x;
    for (int d = 7; d >= 0; --d) {
        int n = 1 << d;
        int half = n >> 1;
        int base = group ? (n - half) : 0;
        int count = group ? half : (n - half);
        int pin = (d + 1) & 1, pout = d & 1;
        if (count > 0) {
            fill_a64(smem, AG(group, 0),
                     g_h[pin] + (size_t)(b * 2 * n + 2 * base) * 64, count, tidl);
            BARG(group);
            float acc[4][5][4] = {};
            do_mma64(smem, sb + AG(group, 0), acc, count, wl, lane);
            stz64(sb, zbase, acc, wl, lane);
            BARG(group);
            epilogue64(smem, zbase, count, x_idx + b * NTREE + (n - 1) + base,
                       g_c[pin] + (size_t)(b * 2 * n + 2 * base) * 64,
                       g_h[pout] + (size_t)(b * n + base) * 64,
                       g_c[pout] + (size_t)(b * n + base) * 64, barr, wl, lane);
        }
        __syncthreads();
    }
}

// ---------------- head
__global__ void head_kernel(const float* __restrict__ W1, const float* __restrict__ b1,
                            const float* __restrict__ W2, const float* __restrict__ b2,
                            const float* __restrict__ W_ih, const float* __restrict__ b_lstm,
                            const float* __restrict__ actorW, const float* __restrict__ actorb,
                            const float* __restrict__ vm, float* __restrict__ out) {
    __shared__ float sh[64], sf1[64], sfeat[128], slog[20], sinv[1];
    int b = blockIdx.x;
    int t = threadIdx.x;
    sh[t] = __bfloat162float(g_h[0][b * 64 + t]);
    __syncthreads();
    float a = 0.f;
    for (int k = 0; k < 64; ++k) a += sh[k] * W1[k * 64 + t];
    a += b1[t];
    sf1[t] = fmaxf(a, 0.f);
    __syncthreads();
    float f = 0.f;
    for (int k = 0; k < 64; ++k) f += sf1[k] * W2[k * 64 + t];
    f += b2[t];
    sfeat[t] = f;
    __syncthreads();
    float gi = 0.f, gg = 0.f, go = 0.f;
    for (int k = 0; k < 64; ++k) {
        float fk = sfeat[k];
        gi += fk * W_ih[k * 256 + t];
        gg += fk * W_ih[k * 256 + 128 + t];
        go += fk * W_ih[k * 256 + 192 + t];
    }
    gi += b_lstm[t];
    gg += b_lstm[128 + t];
    go += b_lstm[192 + t];
    float cg = (1.f / (1.f + expf(-gi))) * tanhf(gg);
    float hg = (1.f / (1.f + expf(-go))) * tanhf(cg);
    sfeat[64 + t] = hg;
    __syncthreads();
    if (t < 20) {
        float l = 0.f;
        for (int dd = 0; dd < 128; ++dd) l += sfeat[dd] * actorW[dd * 20 + t];
        l = logf(vm[t]) + l * vm[t] + actorb[t] * vm[t];
        slog[t] = l / 3.0f;
    }
    __syncthreads();
    if (t == 0) {
        float mx = slog[0];
        for (int k = 1; k < 20; ++k) mx = fmaxf(mx, slog[k]);
        float s = 0.f;
        for (int k = 0; k < 20; ++k) {
            float e = expf(slog[k] - mx);
            slog[k] = e;
            s += e;
        }
        sinv[0] = 1.f / s;
    }
    __syncthreads();
    if (t < 20) out[b * 20 + t] = slog[t] * sinv[0];
}

extern "C" void kernel_launch(void* const* d_in, const int* in_sizes, int n_in,
                              void* d_out, int out_size) {
    const int*   x_idx  = (const int*)d_in[0];
    const float* vm     = (const float*)d_in[1];
    const float* Wx     = (const float*)d_in[2];
    const float* Ua     = (const float*)d_in[3];
    const float* Ub     = (const float*)d_in[4];
    const float* bt     = (const float*)d_in[5];
    const float* W_ih   = (const float*)d_in[6];
    const float* b_lstm = (const float*)d_in[8];
    const float* W1     = (const float*)d_in[9];
    const float* b1     = (const float*)d_in[10];
    const float* W2     = (const float*)d_in[11];
    const float* b2     = (const float*)d_in[12];
    const float* actorW = (const float*)d_in[13];
    const float* actorb = (const float*)d_in[14];
    float* out = (float*)d_out;

    cudaFuncSetAttribute(level_mma, cudaFuncAttributeMaxDynamicSharedMemorySize, SMEM_TOTAL);
    cudaFuncSetAttribute(top_mma, cudaFuncAttributeMaxDynamicSharedMemorySize, SMEM_TOTAL);

    prep_kernel<<<80, 256>>>(Ua, Ub, Wx);
    leaf_kernel<<<(BSZ * 2048 * 16) / 256, 256>>>(x_idx, bt);

    for (int d = 10; d >= 8; --d) {
        int ntile = 2 << d;
        int grid = (ntile + 1) / 2 < 152 ? (ntile + 1) / 2 : 152;
        level_mma<<<grid, NT, SMEM_TOTAL>>>(d, x_idx, bt, (d + 1) & 1, d & 1);
    }
    top_mma<<<BSZ, NT, SMEM_TOTAL>>>(x_idx, bt);

    head_kernel<<<BSZ, 64>>>(W1, b1, W2, b2, W_ih, b_lstm, actorW, actorb, vm, out);
}